// round 3
// baseline (speedup 1.0000x reference)
#include <cuda_runtime.h>
#include <math.h>

#define B_ 2
#define L_ 512
#define C_ 256
#define H_ 8
#define D_ 32
#define SCALE_ 0.17677669529663687f   // 1/sqrt(32)

typedef unsigned long long ull;

// ---------------- f32x2 packed-FMA helpers (sm_103a) ------------------------
__device__ __forceinline__ ull pack2(float a, float b) {
    ull r; asm("mov.b64 %0, {%1, %2};" : "=l"(r) : "f"(a), "f"(b)); return r;
}
__device__ __forceinline__ void unpack2(ull v, float& a, float& b) {
    asm("mov.b64 {%0, %1}, %2;" : "=f"(a), "=f"(b) : "l"(v));
}
__device__ __forceinline__ void ffma2(ull& d, ull a, ull b) {
    asm("fma.rn.f32x2 %0, %1, %2, %0;" : "+l"(d) : "l"(a), "l"(b));
}

// ------------------------- scratch (device globals) -------------------------
__device__ float g_q[B_*H_*L_*D_];          // 1 MB  [b][h][l][d]
__device__ float g_k[B_*H_*L_*D_];          // 1 MB
__device__ float g_v[B_*H_*L_*D_];          // 1 MB
__device__ float g_att[B_*L_*C_];           // 1 MB  [b][l][h*32+d]

// ===========================================================================
// GEMM: out[m][n] = sum_k A[m][k] * W[n][k]   32x32 tile, 128 threads.
// m-pair accumulators (f32x2), W duplicated-pair smem (no pack in mainloop).
// mode 0: A=x, W=[768][256] -> scatter g_q/g_k/g_v.  mode 1: A=g_att, +bias.
// ===========================================================================
__global__ __launch_bounds__(128) void gemm_kernel(
    const float* __restrict__ A, const float* __restrict__ W,
    const float* __restrict__ bias, float* __restrict__ out, int mode)
{
    __shared__ __align__(16) float As[32][34];   // [k][m]
    __shared__ __align__(16) float Wd[32][68];   // [k][n dup-pairs]
    const float* Ap = (mode == 0) ? A : g_att;
    int tid  = threadIdx.x;
    int row0 = blockIdx.x * 32;
    int col0 = blockIdx.y * 32;
    int tx = tid & 7, ty = tid >> 3;             // tx: 4n, ty: m-pair

    ull acc2[4] = {0ull, 0ull, 0ull, 0ull};

    for (int kc = 0; kc < 256; kc += 32) {
        #pragma unroll
        for (int i = 0; i < 2; i++) {
            int idx = tid + i * 128;
            int r = idx & 31, c4 = idx >> 5;
            float4 av = *(const float4*)&Ap[(size_t)(row0 + r) * 256 + kc + c4 * 4];
            As[c4*4+0][r] = av.x; As[c4*4+1][r] = av.y;
            As[c4*4+2][r] = av.z; As[c4*4+3][r] = av.w;
        }
        #pragma unroll
        for (int i = 0; i < 2; i++) {
            int idx = tid + i * 128;
            int n = idx & 31, c4 = idx >> 5;
            float4 wv = *(const float4*)&W[(size_t)(col0 + n) * 256 + kc + c4 * 4];
            Wd[c4*4+0][n*2] = wv.x; Wd[c4*4+0][n*2+1] = wv.x;
            Wd[c4*4+1][n*2] = wv.y; Wd[c4*4+1][n*2+1] = wv.y;
            Wd[c4*4+2][n*2] = wv.z; Wd[c4*4+2][n*2+1] = wv.z;
            Wd[c4*4+3][n*2] = wv.w; Wd[c4*4+3][n*2+1] = wv.w;
        }
        __syncthreads();
        #pragma unroll
        for (int kk = 0; kk < 32; kk++) {
            ull a2 = *(const ull*)&As[kk][ty * 2];            // (a[m0],a[m1])
            ulonglong2 w01 = *(const ulonglong2*)&Wd[kk][tx * 8];
            ulonglong2 w23 = *(const ulonglong2*)&Wd[kk][tx * 8 + 4];
            ffma2(acc2[0], a2, w01.x); ffma2(acc2[1], a2, w01.y);
            ffma2(acc2[2], a2, w23.x); ffma2(acc2[3], a2, w23.y);
        }
        __syncthreads();
    }

    #pragma unroll
    for (int j = 0; j < 4; j++) {
        float v0, v1;
        unpack2(acc2[j], v0, v1);
        int n = col0 + tx * 4 + j;
        #pragma unroll
        for (int half = 0; half < 2; half++) {
            int m = row0 + ty * 2 + half;
            float val = half ? v1 : v0;
            int bb = m >> 9, l = m & 511;
            if (mode == 0) {
                int s = n >> 8, rem = n & 255, h = rem >> 5, d = rem & 31;
                float* dst = (s == 0) ? g_q : (s == 1) ? g_k : g_v;
                dst[(((size_t)bb * H_ + h) * L_ + l) * D_ + d] = val;
            } else {
                out[(size_t)m * 256 + n] = val + bias[n];
            }
        }
    }
}

// ===========================================================================
// FUSED rel-bias + attention.  Block = (b,l), 256 threads, 2 m-rows/thread.
// Streams rp[b,l,:,:] (512KB) straight from HBM; k,v from L2; softmax+PV
// in-block; writes only g_att.  g_rel eliminated.
// ===========================================================================
__global__ __launch_bounds__(256) void fused_kernel(
    const float* __restrict__ rp, const float* __restrict__ w_rel,
    const float* __restrict__ b_rel, const float* __restrict__ ln_g,
    const float* __restrict__ ln_b)
{
    __shared__ __align__(16) float wp[2048];       // weight (c,c+1)-pairs, 8KB
    __shared__ __align__(16) float q_s[8 * 32];    // q rows for all h, 1KB
    __shared__ __align__(16) float lg[8 * 512];    // logits/probs, 16KB
    __shared__ __align__(16) float pp[256 * 4];    // PV partials, 4KB
    __shared__ float par[24];                      // b_rel | gamma | beta
    __shared__ float inv_s[8];

    int tid = threadIdx.x;
    int bid = blockIdx.x;
    int b = bid >> 9, l = bid & 511;

    // --- stage weights as pairs: wp[(c2*4+h2)*4 + e] ------------------------
    #pragma unroll
    for (int i = 0; i < 8; i++) {
        int idx = tid + i * 256;
        int e = idx & 3, h2 = (idx >> 2) & 3, c2 = idx >> 4;
        int h = 2 * h2 + (e >> 1), c = 2 * c2 + (e & 1);
        wp[idx] = w_rel[h * 256 + c];
    }
    { int h = tid >> 5, d = tid & 31;
      q_s[tid] = g_q[(((size_t)b * H_ + h) * L_ + l) * D_ + d]; }
    if (tid < 8) { par[tid] = b_rel[tid]; par[8+tid] = ln_g[tid]; par[16+tid] = ln_b[tid]; }
    __syncthreads();

    int m0 = tid, m1 = tid + 256;
    const float* rpr0 = rp + (((size_t)bid) * 512 + m0) * 256;
    const float* rpr1 = rp + (((size_t)bid) * 512 + m1) * 256;

    // --- rel GEMV for both rows: ra*[h] = (even-c, odd-c) partials ----------
    ull raA[8], raB[8];
    #pragma unroll
    for (int h = 0; h < 8; h++) { raA[h] = 0ull; raB[h] = 0ull; }

    #pragma unroll 8
    for (int c4 = 0; c4 < 64; c4++) {
        ulonglong2 r0 = *(const ulonglong2*)&rpr0[c4 * 4];
        ulonglong2 r1 = *(const ulonglong2*)&rpr1[c4 * 4];
        int c2 = c4 * 2;
        #pragma unroll
        for (int h2 = 0; h2 < 4; h2++) {
            ulonglong2 wA = *(const ulonglong2*)&wp[(c2 * 4 + h2) * 4];
            ulonglong2 wB = *(const ulonglong2*)&wp[((c2 + 1) * 4 + h2) * 4];
            ffma2(raA[2*h2],   r0.x, wA.x); ffma2(raA[2*h2+1], r0.x, wA.y);
            ffma2(raA[2*h2],   r0.y, wB.x); ffma2(raA[2*h2+1], r0.y, wB.y);
            ffma2(raB[2*h2],   r1.x, wA.x); ffma2(raB[2*h2+1], r1.x, wA.y);
            ffma2(raB[2*h2],   r1.y, wB.x); ffma2(raB[2*h2+1], r1.y, wB.y);
        }
    }

    // --- bias + exact GELU + LayerNoram over h, per row ----------------------
    float relA[8], relB[8];
    {
        float muA = 0.f, muB = 0.f;
        #pragma unroll
        for (int h = 0; h < 8; h++) {
            float lo, hi;
            unpack2(raA[h], lo, hi);
            float xv = lo + hi + par[h];
            relA[h] = 0.5f * xv * (1.f + erff(xv * 0.7071067811865475f));
            muA += relA[h];
            unpack2(raB[h], lo, hi);
            xv = lo + hi + par[h];
            relB[h] = 0.5f * xv * (1.f + erff(xv * 0.7071067811865475f));
            muB += relB[h];
        }
        muA *= 0.125f; muB *= 0.125f;
        float vA = 0.f, vB = 0.f;
        #pragma unroll
        for (int h = 0; h < 8; h++) {
            float dA = relA[h] - muA; vA += dA * dA;
            float dB = relB[h] - muB; vB += dB * dB;
        }
        float rA = rsqrtf(vA * 0.125f + 1e-5f), rB = rsqrtf(vB * 0.125f + 1e-5f);
        #pragma unroll
        for (int h = 0; h < 8; h++) {
            relA[h] = (relA[h] - muA) * rA * par[8+h] + par[16+h];
            relB[h] = (relB[h] - muB) * rB * par[8+h] + par[16+h];
        }
    }

    // --- q.k for both rows, all h; write logits ------------------------------
    #pragma unroll
    for (int h = 0; h < 8; h++) {
        const float* kb = g_k + (((size_t)b * H_ + h) * L_) * D_;
        ull sA = 0ull, sB = 0ull;
        #pragma unroll
        for (int j = 0; j < 8; j++) {
            ulonglong2 q2 = *(const ulonglong2*)&q_s[h * 32 + j * 4];
            ulonglong2 kA = *(const ulonglong2*)&kb[(size_t)m0 * 32 + j * 4];
            ulonglong2 kB = *(const ulonglong2*)&kb[(size_t)m1 * 32 + j * 4];
            ffma2(sA, q2.x, kA.x); ffma2(sA, q2.y, kA.y);
            ffma2(sB, q2.x, kB.x); ffma2(sB, q2.y, kB.y);
        }
        float lo, hi;
        unpack2(sA, lo, hi);
        lg[h * 512 + m0] = (lo + hi + relA[h]) * SCALE_;
        unpack2(sB, lo, hi);
        lg[h * 512 + m1] = (lo + hi + relB[h]) * SCALE_;
    }
    __syncthreads();

    // --- softmax: warp w handles h = w ---------------------------------------
    {
        int lane = tid & 31, h = tid >> 5;
        float* row = &lg[h * 512];
        float vals[16];
        float mx = -1e30f;
        #pragma unroll
        for (int j = 0; j < 16; j++) { vals[j] = row[lane + 32 * j]; mx = fmaxf(mx, vals[j]); }
        #pragma unroll
        for (int o = 16; o > 0; o >>= 1) mx = fmaxf(mx, __shfl_xor_sync(0xffffffff, mx, o));
        float sum = 0.f;
        #pragma unroll
        for (int j = 0; j < 16; j++) {
            float e = __expf(vals[j] - mx);
            row[lane + 32 * j] = e;
            sum += e;
        }
        #pragma unroll
        for (int o = 16; o > 0; o >>= 1) sum += __shfl_xor_sync(0xffffffff, sum, o);
        if (lane == 0) inv_s[h] = 1.f / sum;
    }
    __syncthreads();

    // --- PV: thread = (slice s, h, d-quad); 128 m per slice ------------------
    {
        int s = tid >> 6, hd = tid & 63, h = hd >> 3, dq = hd & 7;
        const float* vb = g_v + (((size_t)b * H_ + h) * L_ + s * 128) * D_ + dq * 4;
        const float* lrow = &lg[h * 512 + s * 128];
        ull p0 = 0ull, p1 = 0ull;
        #pragma unroll 4
        for (int mm = 0; mm < 128; mm++) {
            float p = lrow[mm];
            ull pd = pack2(p, p);
            ulonglong2 v2 = *(const ulonglong2*)&vb[(size_t)mm * 32];
            ffma2(p0, pd, v2.x); ffma2(p1, pd, v2.y);
        }
        float a0, a1, a2, a3;
        unpack2(p0, a0, a1); unpack2(p1, a2, a3);
        *(float4*)&pp[tid * 4] = make_float4(a0, a1, a2, a3);
    }
    __syncthreads();
    if (tid < 64) {
        int h = tid >> 3, dq = tid & 7;
        float4 t0 = *(const float4*)&pp[tid * 4];
        float4 t1 = *(const float4*)&pp[(tid + 64) * 4];
        float4 t2 = *(const float4*)&pp[(tid + 128) * 4];
        float4 t3 = *(const float4*)&pp[(tid + 192) * 4];
        float inv = inv_s[h];
        float4 o;
        o.x = (t0.x + t1.x + t2.x + t3.x) * inv;
        o.y = (t0.y + t1.y + t2.y + t3.y) * inv;
        o.z = (t0.z + t1.z + t2.z + t3.z) * inv;
        o.w = (t0.w + t1.w + t2.w + t3.w) * inv;
        *(float4*)&g_att[((size_t)bid) * 256 + h * 32 + dq * 4] = o;
    }
}

// ===========================================================================
extern "C" void kernel_launch(void* const* d_in, const int* in_sizes, int n_in,
                              void* d_out, int out_size)
{
    const float* x      = (const float*)d_in[0];
    const float* rp     = (const float*)d_in[1];
    const float* w_qkv  = (const float*)d_in[2];
    const float* w_rel  = (const float*)d_in[3];
    const float* b_rel  = (const float*)d_in[4];
    const float* ln_g   = (const float*)d_in[5];
    const float* ln_b   = (const float*)d_in[6];
    const float* w_proj = (const float*)d_in[7];
    const float* b_proj = (const float*)d_in[8];
    float* out = (float*)d_out;

    // K1: qkv projection (grid 768 blocks)
    gemm_kernel<<<dim3(32, 24), 128>>>(x, w_qkv, nullptr, nullptr, 0);
    // K2: fused rel-bias + attention (grid 1024 blocks, HBM-bound)
    fused_kernel<<<1024, 256>>>(rp, w_rel, b_rel, ln_g, ln_b);
    // K3: output projection + bias (grid 256 blocks)
    gemm_kernel<<<dim3(32, 8), 128>>>(nullptr, w_proj, b_proj, out, 1);
}

// round 4
// speedup vs baseline: 1.0066x; 1.0066x over previous
#include <cuda_runtime.h>
#include <math.h>

#define B_ 2
#define L_ 512
#define C_ 256
#define H_ 8
#define D_ 32
#define SCALE_ 0.17677669529663687f   // 1/sqrt(32)

typedef unsigned long long ull;

// ---------------- f32x2 packed-FMA helpers (sm_103a) ------------------------
__device__ __forceinline__ ull pack2(float a, float b) {
    ull r; asm("mov.b64 %0, {%1, %2};" : "=l"(r) : "f"(a), "f"(b)); return r;
}
__device__ __forceinline__ void unpack2(ull v, float& a, float& b) {
    asm("mov.b64 {%0, %1}, %2;" : "=f"(a), "=f"(b) : "l"(v));
}
__device__ __forceinline__ void ffma2(ull& d, ull a, ull b) {
    asm("fma.rn.f32x2 %0, %1, %2, %0;" : "+l"(d) : "l"(a), "l"(b));
}

// ------------------------- scratch (device globals) -------------------------
__device__ float g_q[B_*H_*L_*D_];          // 1 MB  [b][h][l][d]
__device__ float g_k[B_*H_*L_*D_];          // 1 MB
__device__ float g_v[B_*H_*L_*D_];          // 1 MB
__device__ float g_att[B_*L_*C_];           // 1 MB  [b][l][h*32+d]

// ===========================================================================
// GEMM: out[m][n] = sum_k A[m][k] * W[n][k]   32x32 tile, 128 threads.
// m-pair accumulators (f32x2), W duplicated-pair smem (no pack in mainloop).
// mode 0: A=x, W=[768][256] -> scatter g_q/g_k/g_v.  mode 1: A=g_att, +bias.
// ===========================================================================
__global__ __launch_bounds__(128) void gemm_kernel(
    const float* __restrict__ A, const float* __restrict__ W,
    const float* __restrict__ bias, float* __restrict__ out, int mode)
{
    __shared__ __align__(16) float As[32][34];   // [k][m]
    __shared__ __align__(16) float Wd[32][68];   // [k][n dup-pairs]
    const float* Ap = (mode == 0) ? A : g_att;
    int tid  = threadIdx.x;
    int row0 = blockIdx.x * 32;
    int col0 = blockIdx.y * 32;
    int tx = tid & 7, ty = tid >> 3;             // tx: 4n, ty: m-pair

    ull acc2[4] = {0ull, 0ull, 0ull, 0ull};

    for (int kc = 0; kc < 256; kc += 32) {
        #pragma unroll
        for (int i = 0; i < 2; i++) {
            int idx = tid + i * 128;
            int r = idx & 31, c4 = idx >> 5;
            float4 av = *(const float4*)&Ap[(size_t)(row0 + r) * 256 + kc + c4 * 4];
            As[c4*4+0][r] = av.x; As[c4*4+1][r] = av.y;
            As[c4*4+2][r] = av.z; As[c4*4+3][r] = av.w;
        }
        #pragma unroll
        for (int i = 0; i < 2; i++) {
            int idx = tid + i * 128;
            int n = idx & 31, c4 = idx >> 5;
            float4 wv = *(const float4*)&W[(size_t)(col0 + n) * 256 + kc + c4 * 4];
            Wd[c4*4+0][n*2] = wv.x; Wd[c4*4+0][n*2+1] = wv.x;
            Wd[c4*4+1][n*2] = wv.y; Wd[c4*4+1][n*2+1] = wv.y;
            Wd[c4*4+2][n*2] = wv.z; Wd[c4*4+2][n*2+1] = wv.z;
            Wd[c4*4+3][n*2] = wv.w; Wd[c4*4+3][n*2+1] = wv.w;
        }
        __syncthreads();
        #pragma unroll
        for (int kk = 0; kk < 32; kk++) {
            ull a2 = *(const ull*)&As[kk][ty * 2];            // (a[m0],a[m1])
            ulonglong2 w01 = *(const ulonglong2*)&Wd[kk][tx * 8];
            ulonglong2 w23 = *(const ulonglong2*)&Wd[kk][tx * 8 + 4];
            ffma2(acc2[0], a2, w01.x); ffma2(acc2[1], a2, w01.y);
            ffma2(acc2[2], a2, w23.x); ffma2(acc2[3], a2, w23.y);
        }
        __syncthreads();
    }

    #pragma unroll
    for (int j = 0; j < 4; j++) {
        float v0, v1;
        unpack2(acc2[j], v0, v1);
        int n = col0 + tx * 4 + j;
        #pragma unroll
        for (int half = 0; half < 2; half++) {
            int m = row0 + ty * 2 + half;
            float val = half ? v1 : v0;
            int bb = m >> 9, l = m & 511;
            if (mode == 0) {
                int s = n >> 8, rem = n & 255, h = rem >> 5, d = rem & 31;
                float* dst = (s == 0) ? g_q : (s == 1) ? g_k : g_v;
                dst[(((size_t)bb * H_ + h) * L_ + l) * D_ + d] = val;
            } else {
                out[(size_t)m * 256 + n] = val + bias[n];
            }
        }
    }
}

// ===========================================================================
// FUSED rel-bias + attention.  Block = (b,l), 256 threads, 2 m-rows/thread.
// Streams rp[b,l,:,:] (512KB) straight from HBM; k,v from L2; softmax+PV
// in-block; writes only g_att.  g_rel eliminated.
// ===========================================================================
__global__ __launch_bounds__(256) void fused_kernel(
    const float* __restrict__ rp, const float* __restrict__ w_rel,
    const float* __restrict__ b_rel, const float* __restrict__ ln_g,
    const float* __restrict__ ln_b)
{
    __shared__ __align__(16) float wp[2048];       // weight (c,c+1)-pairs, 8KB
    __shared__ __align__(16) float q_s[8 * 32];    // q rows for all h, 1KB
    __shared__ __align__(16) float lg[8 * 512];    // logits/probs, 16KB
    __shared__ __align__(16) float pp[256 * 4];    // PV partials, 4KB
    __shared__ float par[24];                      // b_rel | gamma | beta
    __shared__ float inv_s[8];

    int tid = threadIdx.x;
    int bid = blockIdx.x;
    int b = bid >> 9, l = bid & 511;

    // --- stage weights as pairs: wp[(c2*4+h2)*4 + e] ------------------------
    #pragma unroll
    for (int i = 0; i < 8; i++) {
        int idx = tid + i * 256;
        int e = idx & 3, h2 = (idx >> 2) & 3, c2 = idx >> 4;
        int h = 2 * h2 + (e >> 1), c = 2 * c2 + (e & 1);
        wp[idx] = w_rel[h * 256 + c];
    }
    { int h = tid >> 5, d = tid & 31;
      q_s[tid] = g_q[(((size_t)b * H_ + h) * L_ + l) * D_ + d]; }
    if (tid < 8) { par[tid] = b_rel[tid]; par[8+tid] = ln_g[tid]; par[16+tid] = ln_b[tid]; }
    __syncthreads();

    int m0 = tid, m1 = tid + 256;
    const float* rpr0 = rp + (((size_t)bid) * 512 + m0) * 256;
    const float* rpr1 = rp + (((size_t)bid) * 512 + m1) * 256;

    // --- rel GEMV for both rows: ra*[h] = (even-c, odd-c) partials ----------
    ull raA[8], raB[8];
    #pragma unroll
    for (int h = 0; h < 8; h++) { raA[h] = 0ull; raB[h] = 0ull; }

    #pragma unroll 8
    for (int c4 = 0; c4 < 64; c4++) {
        ulonglong2 r0 = *(const ulonglong2*)&rpr0[c4 * 4];
        ulonglong2 r1 = *(const ulonglong2*)&rpr1[c4 * 4];
        int c2 = c4 * 2;
        #pragma unroll
        for (int h2 = 0; h2 < 4; h2++) {
            ulonglong2 wA = *(const ulonglong2*)&wp[(c2 * 4 + h2) * 4];
            ulonglong2 wB = *(const ulonglong2*)&wp[((c2 + 1) * 4 + h2) * 4];
            ffma2(raA[2*h2],   r0.x, wA.x); ffma2(raA[2*h2+1], r0.x, wA.y);
            ffma2(raA[2*h2],   r0.y, wB.x); ffma2(raA[2*h2+1], r0.y, wB.y);
            ffma2(raB[2*h2],   r1.x, wA.x); ffma2(raB[2*h2+1], r1.x, wA.y);
            ffma2(raB[2*h2],   r1.y, wB.x); ffma2(raB[2*h2+1], r1.y, wB.y);
        }
    }

    // --- bias + exact GELU + LayerNoram over h, per row ----------------------
    float relA[8], relB[8];
    {
        float muA = 0.f, muB = 0.f;
        #pragma unroll
        for (int h = 0; h < 8; h++) {
            float lo, hi;
            unpack2(raA[h], lo, hi);
            float xv = lo + hi + par[h];
            relA[h] = 0.5f * xv * (1.f + erff(xv * 0.7071067811865475f));
            muA += relA[h];
            unpack2(raB[h], lo, hi);
            xv = lo + hi + par[h];
            relB[h] = 0.5f * xv * (1.f + erff(xv * 0.7071067811865475f));
            muB += relB[h];
        }
        muA *= 0.125f; muB *= 0.125f;
        float vA = 0.f, vB = 0.f;
        #pragma unroll
        for (int h = 0; h < 8; h++) {
            float dA = relA[h] - muA; vA += dA * dA;
            float dB = relB[h] - muB; vB += dB * dB;
        }
        float rA = rsqrtf(vA * 0.125f + 1e-5f), rB = rsqrtf(vB * 0.125f + 1e-5f);
        #pragma unroll
        for (int h = 0; h < 8; h++) {
            relA[h] = (relA[h] - muA) * rA * par[8+h] + par[16+h];
            relB[h] = (relB[h] - muB) * rB * par[8+h] + par[16+h];
        }
    }

    // --- q.k for both rows, all h; write logits ------------------------------
    #pragma unroll
    for (int h = 0; h < 8; h++) {
        const float* kb = g_k + (((size_t)b * H_ + h) * L_) * D_;
        ull sA = 0ull, sB = 0ull;
        #pragma unroll
        for (int j = 0; j < 8; j++) {
            ulonglong2 q2 = *(const ulonglong2*)&q_s[h * 32 + j * 4];
            ulonglong2 kA = *(const ulonglong2*)&kb[(size_t)m0 * 32 + j * 4];
            ulonglong2 kB = *(const ulonglong2*)&kb[(size_t)m1 * 32 + j * 4];
            ffma2(sA, q2.x, kA.x); ffma2(sA, q2.y, kA.y);
            ffma2(sB, q2.x, kB.x); ffma2(sB, q2.y, kB.y);
        }
        float lo, hi;
        unpack2(sA, lo, hi);
        lg[h * 512 + m0] = (lo + hi + relA[h]) * SCALE_;
        unpack2(sB, lo, hi);
        lg[h * 512 + m1] = (lo + hi + relB[h]) * SCALE_;
    }
    __syncthreads();

    // --- softmax: warp w handles h = w ---------------------------------------
    {
        int lane = tid & 31, h = tid >> 5;
        float* row = &lg[h * 512];
        float vals[16];
        float mx = -1e30f;
        #pragma unroll
        for (int j = 0; j < 16; j++) { vals[j] = row[lane + 32 * j]; mx = fmaxf(mx, vals[j]); }
        #pragma unroll
        for (int o = 16; o > 0; o >>= 1) mx = fmaxf(mx, __shfl_xor_sync(0xffffffff, mx, o));
        float sum = 0.f;
        #pragma unroll
        for (int j = 0; j < 16; j++) {
            float e = __expf(vals[j] - mx);
            row[lane + 32 * j] = e;
            sum += e;
        }
        #pragma unroll
        for (int o = 16; o > 0; o >>= 1) sum += __shfl_xor_sync(0xffffffff, sum, o);
        if (lane == 0) inv_s[h] = 1.f / sum;
    }
    __syncthreads();

    // --- PV: thread = (slice s, h, d-quad); 128 m per slice ------------------
    {
        int s = tid >> 6, hd = tid & 63, h = hd >> 3, dq = hd & 7;
        const float* vb = g_v + (((size_t)b * H_ + h) * L_ + s * 128) * D_ + dq * 4;
        const float* lrow = &lg[h * 512 + s * 128];
        ull p0 = 0ull, p1 = 0ull;
        #pragma unroll 4
        for (int mm = 0; mm < 128; mm++) {
            float p = lrow[mm];
            ull pd = pack2(p, p);
            ulonglong2 v2 = *(const ulonglong2*)&vb[(size_t)mm * 32];
            ffma2(p0, pd, v2.x); ffma2(p1, pd, v2.y);
        }
        float a0, a1, a2, a3;
        unpack2(p0, a0, a1); unpack2(p1, a2, a3);
        *(float4*)&pp[tid * 4] = make_float4(a0, a1, a2, a3);
    }
    __syncthreads();
    if (tid < 64) {
        int h = tid >> 3, dq = tid & 7;
        float4 t0 = *(const float4*)&pp[tid * 4];
        float4 t1 = *(const float4*)&pp[(tid + 64) * 4];
        float4 t2 = *(const float4*)&pp[(tid + 128) * 4];
        float4 t3 = *(const float4*)&pp[(tid + 192) * 4];
        float inv = inv_s[h];
        float4 o;
        o.x = (t0.x + t1.x + t2.x + t3.x) * inv;
        o.y = (t0.y + t1.y + t2.y + t3.y) * inv;
        o.z = (t0.z + t1.z + t2.z + t3.z) * inv;
        o.w = (t0.w + t1.w + t2.w + t3.w) * inv;
        *(float4*)&g_att[((size_t)bid) * 256 + h * 32 + dq * 4] = o;
    }
}

// ===========================================================================
extern "C" void kernel_launch(void* const* d_in, const int* in_sizes, int n_in,
                              void* d_out, int out_size)
{
    const float* x      = (const float*)d_in[0];
    const float* rp     = (const float*)d_in[1];
    const float* w_qkv  = (const float*)d_in[2];
    const float* w_rel  = (const float*)d_in[3];
    const float* b_rel  = (const float*)d_in[4];
    const float* ln_g   = (const float*)d_in[5];
    const float* ln_b   = (const float*)d_in[6];
    const float* w_proj = (const float*)d_in[7];
    const float* b_proj = (const float*)d_in[8];
    float* out = (float*)d_out;

    // K1: qkv projection (grid 768 blocks)
    gemm_kernel<<<dim3(32, 24), 128>>>(x, w_qkv, nullptr, nullptr, 0);
    // K2: fused rel-bias + attention (grid 1024 blocks, HBM-bound)
    fused_kernel<<<1024, 256>>>(rp, w_rel, b_rel, ln_g, ln_b);
    // K3: output projection + bias (grid 256 blocks)
    gemm_kernel<<<dim3(32, 8), 128>>>(nullptr, w_proj, b_proj, out, 1);
}

// round 5
// speedup vs baseline: 2.3448x; 2.3295x over previous
#include <cuda_runtime.h>
#include <math.h>

#define B_ 2
#define L_ 512
#define C_ 256
#define H_ 8
#define D_ 32
#define SCALE_ 0.17677669529663687f   // 1/sqrt(32)

typedef unsigned long long ull;

// ---------------- f32x2 packed-FMA helpers (sm_103a) ------------------------
__device__ __forceinline__ ull pack2(float a, float b) {
    ull r; asm("mov.b64 %0, {%1, %2};" : "=l"(r) : "f"(a), "f"(b)); return r;
}
__device__ __forceinline__ void unpack2(ull v, float& a, float& b) {
    asm("mov.b64 {%0, %1}, %2;" : "=f"(a), "=f"(b) : "l"(v));
}
__device__ __forceinline__ void ffma2(ull& d, ull a, ull b) {
    asm("fma.rn.f32x2 %0, %1, %2, %0;" : "+l"(d) : "l"(a), "l"(b));
}

// ------------------------- scratch (device globals) -------------------------
__device__ float g_q[B_*H_*L_*D_];          // 1 MB  [b][h][l][d]
__device__ float g_k[B_*H_*L_*D_];          // 1 MB
__device__ float g_v[B_*H_*L_*D_];          // 1 MB
__device__ float g_qk[B_*L_*H_*L_];         // 16 MB [b][l][h][m]  (q.k logits)
__device__ float g_p [B_*L_*H_*L_];         // 16 MB [b][l][h][m]  (normalized probs)
__device__ float g_att[B_*L_*C_];           // 1 MB  [b][l][h*32+d]

// ===========================================================================
// K1/K5 GEMM (round-2 proven): out[m][n] = sum_k A[m][k]*W[n][k]
// 64x32 tile, 128 threads, 4x4 micro via f32x2 m-pairs.
// mode 0: A=x, W=[768][256] -> scatter g_q/g_k/g_v.  mode 1: A=g_att, +bias.
// ===========================================================================
__global__ __launch_bounds__(128) void gemm_kernel(
    const float* __restrict__ A, const float* __restrict__ W,
    const float* __restrict__ bias, float* __restrict__ out, int mode)
{
    __shared__ __align__(16) float As[32][68];
    __shared__ __align__(16) float Ws[32][36];
    const float* Ap = (mode == 0) ? A : g_att;
    int tid  = threadIdx.x;
    int row0 = blockIdx.x * 64;
    int col0 = blockIdx.y * 32;
    int tx = tid & 7, ty = tid >> 3;

    ull acc2[2][4];
    #pragma unroll
    for (int i = 0; i < 2; i++)
        #pragma unroll
        for (int j = 0; j < 4; j++) acc2[i][j] = 0ull;

    for (int kc = 0; kc < 256; kc += 32) {
        #pragma unroll
        for (int i = 0; i < 4; i++) {
            int idx = tid + i * 128;
            int r = idx >> 3, c4 = idx & 7;
            float4 av = *(const float4*)&Ap[(size_t)(row0 + r) * 256 + kc + c4 * 4];
            As[c4*4+0][r] = av.x; As[c4*4+1][r] = av.y;
            As[c4*4+2][r] = av.z; As[c4*4+3][r] = av.w;
        }
        #pragma unroll
        for (int i = 0; i < 2; i++) {
            int idx = tid + i * 128;
            int r = idx >> 3, c4 = idx & 7;
            float4 wv = *(const float4*)&W[(size_t)(col0 + r) * 256 + kc + c4 * 4];
            Ws[c4*4+0][r] = wv.x; Ws[c4*4+1][r] = wv.y;
            Ws[c4*4+2][r] = wv.z; Ws[c4*4+3][r] = wv.w;
        }
        __syncthreads();
        #pragma unroll
        for (int kk = 0; kk < 32; kk++) {
            ulonglong2 a2 = *(const ulonglong2*)&As[kk][ty * 4];
            float4 b4 = *(const float4*)&Ws[kk][tx * 4];
            ull bd[4] = { pack2(b4.x, b4.x), pack2(b4.y, b4.y),
                          pack2(b4.z, b4.z), pack2(b4.w, b4.w) };
            #pragma unroll
            for (int j = 0; j < 4; j++) {
                ffma2(acc2[0][j], a2.x, bd[j]);
                ffma2(acc2[1][j], a2.y, bd[j]);
            }
        }
        __syncthreads();
    }

    #pragma unroll
    for (int i2 = 0; i2 < 2; i2++) {
        #pragma unroll
        for (int j = 0; j < 4; j++) {
            float v0, v1;
            unpack2(acc2[i2][j], v0, v1);
            int n = col0 + tx * 4 + j;
            #pragma unroll
            for (int half = 0; half < 2; half++) {
                int m  = row0 + ty * 4 + i2 * 2 + half;
                float val = half ? v1 : v0;
                int bb = m >> 9, l = m & 511;
                if (mode == 0) {
                    int s = n >> 8, rem = n & 255, h = rem >> 5, d = rem & 31;
                    float* dst = (s == 0) ? g_q : (s == 1) ? g_k : g_v;
                    dst[(((size_t)bb * H_ + h) * L_ + l) * D_ + d] = val;
                } else {
                    out[(size_t)m * 256 + n] = val + bias[n];
                }
            }
        }
    }
}

// ===========================================================================
// K2: qk[b,l,h,m] = q[b,h,l,:].k[b,h,m,:]   block=(lt, bh), k staged whole.
// ===========================================================================
__global__ __launch_bounds__(256) void qk_kernel()
{
    extern __shared__ __align__(16) float smqk[];
    float* ks = smqk;              // [512][36]
    float* qs = smqk + 512 * 36;   // [32][32]
    int tid = threadIdx.x;
    int bh = blockIdx.y, lt = blockIdx.x;
    int b = bh >> 3, h = bh & 7;

    const float* kb = g_k + (size_t)bh * (512 * 32);
    const float* qb = g_q + (size_t)bh * (512 * 32) + (size_t)lt * 32 * 32;

    #pragma unroll
    for (int i = 0; i < 16; i++) {
        int idx = tid + i * 256;
        int r = idx >> 3, c4 = idx & 7;
        *(float4*)&ks[r * 36 + c4 * 4] = *(const float4*)&kb[(size_t)idx * 4];
    }
    { int r = tid >> 3, c4 = tid & 7;
      *(float4*)&qs[r * 32 + c4 * 4] = *(const float4*)&qb[(size_t)tid * 4]; }
    __syncthreads();

    int l = tid >> 3, mg = tid & 7;
    ull q2[16];
    #pragma unroll
    for (int j = 0; j < 8; j++) {
        ulonglong2 t = *(const ulonglong2*)&qs[l * 32 + j * 4];
        q2[2*j] = t.x; q2[2*j+1] = t.y;
    }
    float* outp = g_qk + (((size_t)b * 512 + lt * 32 + l) * 8 + h) * 512;
    #pragma unroll 4
    for (int i = 0; i < 64; i++) {
        int m = mg + i * 8;
        ull sa = 0ull, sb = 0ull;
        #pragma unroll
        for (int j = 0; j < 8; j++) {
            ulonglong2 kv = *(const ulonglong2*)&ks[m * 36 + j * 4];
            ffma2(sa, q2[2*j], kv.x);
            ffma2(sb, q2[2*j+1], kv.y);
        }
        float a0, a1, b0, b1;
        unpack2(sa, a0, a1); unpack2(sb, b0, b1);
        outp[m] = (a0 + a1) + (b0 + b1);
    }
}

// ===========================================================================
// K3: the HBM-bound hot kernel.  block=(b,l): streams rp[b,l,:,:] (512 KB)
// via coalesced smem staging; rel GEMV (8 h, even/odd-c f32x2 partials);
// GELU+LN; + qk logits; softmax; writes normalized probs to g_p.
// ===========================================================================
#define REL_SMEM_FLOATS (512 * 36 + 2048 + 8 * 512 + 64)

__global__ __launch_bounds__(256) void rel_kernel(
    const float* __restrict__ rp, const float* __restrict__ w_rel,
    const float* __restrict__ b_rel, const float* __restrict__ ln_g,
    const float* __restrict__ ln_b)
{
    extern __shared__ __align__(16) float smr[];
    float* tile = smr;                       // [512][36]  73.7 KB
    float* wp   = smr + 512 * 36;            // 2048: (c2,h2) weight pairs
    float* lg   = wp + 2048;                 // [8][512] logits
    float* par  = lg + 8 * 512;              // 24
    float* inv_s= par + 32;                  // 8

    int tid = threadIdx.x;
    int bid = blockIdx.x;                    // = b*512 + l

    #pragma unroll
    for (int i = 0; i < 8; i++) {
        int idx = tid + i * 256;
        int e = idx & 3, h2 = (idx >> 2) & 3, c2 = idx >> 4;
        int h = 2 * h2 + (e >> 1), c = 2 * c2 + (e & 1);
        wp[idx] = w_rel[h * 256 + c];
    }
    if (tid < 8) { par[tid] = b_rel[tid]; par[8+tid] = ln_g[tid]; par[16+tid] = ln_b[tid]; }

    const float* rpb = rp + (size_t)bid * (512 * 256);
    int m0 = tid, m1 = tid + 256;

    ull raA[8], raB[8];
    #pragma unroll
    for (int h = 0; h < 8; h++) { raA[h] = 0ull; raB[h] = 0ull; }

    for (int ch = 0; ch < 8; ch++) {
        __syncthreads();
        #pragma unroll
        for (int i = 0; i < 16; i++) {                 // stage 512 rows x 32 c
            int idx = tid + i * 256;
            int r = idx >> 3, c4 = idx & 7;
            *(float4*)&tile[r * 36 + c4 * 4] =
                *(const float4*)&rpb[(size_t)r * 256 + ch * 32 + c4 * 4];
        }
        __syncthreads();
        const float* t0 = &tile[m0 * 36];
        const float* t1 = &tile[m1 * 36];
        #pragma unroll
        for (int c4 = 0; c4 < 8; c4++) {
            ulonglong2 r0 = *(const ulonglong2*)&t0[c4 * 4];
            ulonglong2 r1 = *(const ulonglong2*)&t1[c4 * 4];
            int g2 = ch * 16 + c4 * 2;
            #pragma unroll
            for (int h2 = 0; h2 < 4; h2++) {
                ulonglong2 wA = *(const ulonglong2*)&wp[(g2 * 4 + h2) * 4];
                ulonglong2 wB = *(const ulonglong2*)&wp[((g2 + 1) * 4 + h2) * 4];
                ffma2(raA[2*h2],   r0.x, wA.x); ffma2(raA[2*h2+1], r0.x, wA.y);
                ffma2(raA[2*h2],   r0.y, wB.x); ffma2(raA[2*h2+1], r0.y, wB.y);
                ffma2(raB[2*h2],   r1.x, wA.x); ffma2(raB[2*h2+1], r1.x, wA.y);
                ffma2(raB[2*h2],   r1.y, wB.x); ffma2(raB[2*h2+1], r1.y, wB.y);
            }
        }
    }

    // bias + exact GELU + LayerNorm over h, per row
    float relA[8], relB[8];
    {
        float muA = 0.f, muB = 0.f;
        #pragma unroll
        for (int h = 0; h < 8; h++) {
            float lo, hi;
            unpack2(raA[h], lo, hi);
            float xv = lo + hi + par[h];
            relA[h] = 0.5f * xv * (1.f + erff(xv * 0.7071067811865475f));
            muA += relA[h];
            unpack2(raB[h], lo, hi);
            xv = lo + hi + par[h];
            relB[h] = 0.5f * xv * (1.f + erff(xv * 0.7071067811865475f));
            muB += relB[h];
        }
        muA *= 0.125f; muB *= 0.125f;
        float vA = 0.f, vB = 0.f;
        #pragma unroll
        for (int h = 0; h < 8; h++) {
            float dA = relA[h] - muA; vA += dA * dA;
            float dB = relB[h] - muB; vB += dB * dB;
        }
        float rA = rsqrtf(vA * 0.125f + 1e-5f), rB = rsqrtf(vB * 0.125f + 1e-5f);
        #pragma unroll
        for (int h = 0; h < 8; h++) {
            relA[h] = (relA[h] - muA) * rA * par[8+h] + par[16+h];
            relB[h] = (relB[h] - muB) * rB * par[8+h] + par[16+h];
        }
    }

    // add q.k logits, scale, into smem
    const float* qkb = g_qk + (size_t)bid * 4096;
    #pragma unroll
    for (int h = 0; h < 8; h++) {
        lg[h * 512 + m0] = (qkb[h * 512 + m0] + relA[h]) * SCALE_;
        lg[h * 512 + m1] = (qkb[h * 512 + m1] + relB[h]) * SCALE_;
    }
    __syncthreads();

    // softmax: warp per h
    {
        int lane = tid & 31, h = tid >> 5;
        float* row = &lg[h * 512];
        float vals[16];
        float mx = -1e30f;
        #pragma unroll
        for (int j = 0; j < 16; j++) { vals[j] = row[lane + 32 * j]; mx = fmaxf(mx, vals[j]); }
        #pragma unroll
        for (int o = 16; o > 0; o >>= 1) mx = fmaxf(mx, __shfl_xor_sync(0xffffffff, mx, o));
        float sum = 0.f;
        #pragma unroll
        for (int j = 0; j < 16; j++) {
            float e = __expf(vals[j] - mx);
            row[lane + 32 * j] = e;
            sum += e;
        }
        #pragma unroll
        for (int o = 16; o > 0; o >>= 1) sum += __shfl_xor_sync(0xffffffff, sum, o);
        if (lane == 0) inv_s[h] = 1.f / sum;
    }
    __syncthreads();

    // write normalized probs (coalesced float4)
    float* pb = g_p + (size_t)bid * 4096;
    #pragma unroll
    for (int i = 0; i < 4; i++) {
        int idx4 = tid + i * 256;
        int h = idx4 >> 7;
        float4 v = *(const float4*)&lg[h * 512 + (idx4 & 127) * 4];
        float inv = inv_s[h];
        v.x *= inv; v.y *= inv; v.z *= inv; v.w *= inv;
        *(float4*)&pb[(size_t)idx4 * 4] = v;
    }
}

// ===========================================================================
// K4: PV: att[b,l,h,d] = sum_m p[b,l,h,m] * v[b,h,m,d].  v staged whole.
// ===========================================================================
__global__ __launch_bounds__(256) void pv_kernel()
{
    extern __shared__ __align__(16) float smpv[];
    float* vs = smpv;                        // [512][36]
    int tid = threadIdx.x;
    int bh = blockIdx.y, lt = blockIdx.x;
    int b = bh >> 3, h = bh & 7;

    const float* vb = g_v + (size_t)bh * (512 * 32);
    #pragma unroll
    for (int i = 0; i < 16; i++) {
        int idx = tid + i * 256;
        int r = idx >> 3, c4 = idx & 7;
        *(float4*)&vs[r * 36 + c4 * 4] = *(const float4*)&vb[(size_t)idx * 4];
    }
    __syncthreads();

    int l = tid >> 3, dq = tid & 7;
    const float* prow = g_p + (((size_t)b * 512 + lt * 32 + l) * 8 + h) * 512;
    ull a0 = 0ull, a1 = 0ull;
    #pragma unroll 4
    for (int m4 = 0; m4 < 512; m4 += 4) {
        float4 p4 = *(const float4*)&prow[m4];
        float pv[4] = {p4.x, p4.y, p4.z, p4.w};
        #pragma unroll
        for (int s = 0; s < 4; s++) {
            ull pd = pack2(pv[s], pv[s]);
            ulonglong2 v2 = *(const ulonglong2*)&vs[(m4 + s) * 36 + dq * 4];
            ffma2(a0, pd, v2.x);
            ffma2(a1, pd, v2.y);
        }
    }
    float o0, o1, o2, o3;
    unpack2(a0, o0, o1); unpack2(a1, o2, o3);
    *(float4*)&g_att[((size_t)b * 512 + lt * 32 + l) * 256 + h * 32 + dq * 4] =
        make_float4(o0, o1, o2, o3);
}

// ===========================================================================
extern "C" void kernel_launch(void* const* d_in, const int* in_sizes, int n_in,
                              void* d_out, int out_size)
{
    const float* x      = (const float*)d_in[0];
    const float* rp     = (const float*)d_in[1];
    const float* w_qkv  = (const float*)d_in[2];
    const float* w_rel  = (const float*)d_in[3];
    const float* b_rel  = (const float*)d_in[4];
    const float* ln_g   = (const float*)d_in[5];
    const float* ln_b   = (const float*)d_in[6];
    const float* w_proj = (const float*)d_in[7];
    const float* b_proj = (const float*)d_in[8];
    float* out = (float*)d_out;

    int qk_smem  = (512 * 36 + 32 * 32) * (int)sizeof(float);
    int rel_smem = REL_SMEM_FLOATS * (int)sizeof(float);
    int pv_smem  = (512 * 36) * (int)sizeof(float);
    cudaFuncSetAttribute(qk_kernel,  cudaFuncAttributeMaxDynamicSharedMemorySize, qk_smem);
    cudaFuncSetAttribute(rel_kernel, cudaFuncAttributeMaxDynamicSharedMemorySize, rel_smem);
    cudaFuncSetAttribute(pv_kernel,  cudaFuncAttributeMaxDynamicSharedMemorySize, pv_smem);

    // K1: qkv projection
    gemm_kernel<<<dim3(16, 24), 128>>>(x, w_qkv, nullptr, nullptr, 0);
    // K2: qk logits
    qk_kernel<<<dim3(16, 16), 256, qk_smem>>>();
    // K3: rel bias + softmax (HBM-bound, 537 MB stream)
    rel_kernel<<<1024, 256, rel_smem>>>(rp, w_rel, b_rel, ln_g, ln_b);
    // K4: PV
    pv_kernel<<<dim3(16, 16), 256, pv_smem>>>();
    // K5: output projection + bias
    gemm_kernel<<<dim3(16, 8), 128>>>(nullptr, w_proj, b_proj, out, 1);
}